// round 1
// baseline (speedup 1.0000x reference)
#include <cuda_runtime.h>
#include <cstddef>

#define B_TOT 1024
#define NTOK  98
#define DIM   192
#define HEADS 6
#define HD    32
#define NW    64
#define TABLE 507   // (2*2-1)*(13)*(13)

// Scratch (allocation-free rule: __device__ globals)
__device__ float g_kv [ (size_t)B_TOT * NTOK * 2 * DIM ];  // [B, N, 384] = [B,N,2,H,D]
__device__ float g_ctx[ (size_t)B_TOT * NTOK * DIM ];      // [B, N, 192]

// ---------------------------------------------------------------------------
// Tiled fp32 GEMM: C[M,N] = A[M,K] @ W[K,N] + bias[N]
// BM=BN=64, BK=16, 256 threads, 4x4 per-thread tile. All dims divisible.
// ---------------------------------------------------------------------------
__global__ __launch_bounds__(256) void gemm_bias_kernel(
    const float* __restrict__ A, const float* __restrict__ W,
    const float* __restrict__ bias, float* __restrict__ C,
    int K, int N)
{
    __shared__ float As[16][64];   // [k][m] (transposed A tile)
    __shared__ float Ws[16][64];   // [k][n]

    const int tid = threadIdx.x;
    const int tx  = tid & 15;        // 0..15 -> n sub
    const int ty  = tid >> 4;        // 0..15 -> m sub
    const int bm  = blockIdx.y * 64;
    const int bn  = blockIdx.x * 64;

    const int arow = tid >> 2;       // 0..63
    const int ac4  = tid & 3;        // 0..3  (float4 column group)
    const int wrow = tid >> 4;       // 0..15
    const int wc4  = tid & 15;       // 0..15 (float4 column group)

    float acc[4][4] = {};

    for (int kk = 0; kk < K; kk += 16) {
        float4 av = *(const float4*)&A[(size_t)(bm + arow) * K + kk + ac4 * 4];
        As[ac4 * 4 + 0][arow] = av.x;
        As[ac4 * 4 + 1][arow] = av.y;
        As[ac4 * 4 + 2][arow] = av.z;
        As[ac4 * 4 + 3][arow] = av.w;
        *(float4*)&Ws[wrow][wc4 * 4] =
            *(const float4*)&W[(size_t)(kk + wrow) * N + bn + wc4 * 4];
        __syncthreads();

        #pragma unroll
        for (int k = 0; k < 16; k++) {
            float4 a = *(float4*)&As[k][ty * 4];
            float4 b = *(float4*)&Ws[k][tx * 4];
            float ar[4] = {a.x, a.y, a.z, a.w};
            float br[4] = {b.x, b.y, b.z, b.w};
            #pragma unroll
            for (int i = 0; i < 4; i++)
                #pragma unroll
                for (int j = 0; j < 4; j++)
                    acc[i][j] += ar[i] * br[j];
        }
        __syncthreads();
    }

    float4 bv = *(const float4*)&bias[bn + tx * 4];
    float bb[4] = {bv.x, bv.y, bv.z, bv.w};
    #pragma unroll
    for (int i = 0; i < 4; i++) {
        float4 o;
        o.x = acc[i][0] + bb[0];
        o.y = acc[i][1] + bb[1];
        o.z = acc[i][2] + bb[2];
        o.w = acc[i][3] + bb[3];
        *(float4*)&C[(size_t)(bm + ty * 4 + i) * N + bn + tx * 4] = o;
    }
}

// ---------------------------------------------------------------------------
// Fused attention: one block per (head, batch-window). 128 threads (4 warps).
// smem K/V tiles (98x32, padded stride 33 => conflict-free), rpb column,
// per-warp score row. Each warp owns query rows q = warp, warp+4, ...
// ---------------------------------------------------------------------------
__global__ __launch_bounds__(128) void attn_kernel(
    const float* __restrict__ x_up,      // [B, N, DIM]
    const float* __restrict__ mask,      // [NW, N, N]
    const float* __restrict__ rpb,       // [TABLE, HEADS]
    const int*   __restrict__ rel_idx,   // [N, N]
    const float* __restrict__ kv,        // [B, N, 384]
    float*       __restrict__ ctx)       // [B, N, DIM]
{
    const int h = blockIdx.x;
    const int b = blockIdx.y;

    __shared__ float Ks[NTOK][33];
    __shared__ float Vs[NTOK][33];
    __shared__ float rpb_s[TABLE];
    __shared__ float srow[4][NTOK];
    __shared__ float qs[4][HD];

    const int tid  = threadIdx.x;
    const int lane = tid & 31;
    const int w    = tid >> 5;

    const float* kvb = kv + (size_t)b * NTOK * 384;
    for (int i = tid; i < NTOK * HD; i += 128) {
        int j = i >> 5, d = i & 31;
        Ks[j][d] = kvb[(size_t)j * 384 + h * HD + d];
        Vs[j][d] = kvb[(size_t)j * 384 + DIM + h * HD + d];
    }
    for (int i = tid; i < TABLE; i += 128)
        rpb_s[i] = rpb[(size_t)i * HEADS + h];
    __syncthreads();

    const float scale = 0.1767766952966369f;   // 32^-0.5
    const float* maskw = mask + (size_t)(b & (NW - 1)) * NTOK * NTOK;

    for (int q = w; q < NTOK; q += 4) {
        qs[w][lane] = x_up[((size_t)b * NTOK + q) * DIM + h * HD + lane] * scale;
        __syncwarp();

        const int*   relq = rel_idx + q * NTOK;
        const float* mq   = maskw   + (size_t)q * NTOK;

        float mloc = -1e30f;
        #pragma unroll
        for (int t = 0; t < 4; t++) {
            int j = lane + t * 32;
            if (j < NTOK) {
                float acc = 0.f;
                #pragma unroll
                for (int d = 0; d < HD; d++)
                    acc += qs[w][d] * Ks[j][d];
                acc += rpb_s[relq[j]] + mq[j];
                srow[w][j] = acc;
                mloc = fmaxf(mloc, acc);
            }
        }
        #pragma unroll
        for (int o = 16; o > 0; o >>= 1)
            mloc = fmaxf(mloc, __shfl_xor_sync(0xffffffffu, mloc, o));

        float ssum = 0.f;
        #pragma unroll
        for (int t = 0; t < 4; t++) {
            int j = lane + t * 32;
            if (j < NTOK) {
                float e = __expf(srow[w][j] - mloc);
                srow[w][j] = e;
                ssum += e;
            }
        }
        #pragma unroll
        for (int o = 16; o > 0; o >>= 1)
            ssum += __shfl_xor_sync(0xffffffffu, ssum, o);
        const float inv = 1.0f / ssum;
        __syncwarp();

        float acc = 0.f;
        #pragma unroll 7
        for (int j = 0; j < NTOK; j++)
            acc += srow[w][j] * Vs[j][lane];
        ctx[((size_t)b * NTOK + q) * DIM + h * HD + lane] = acc * inv;

        __syncwarp();
    }
}

// ---------------------------------------------------------------------------
extern "C" void kernel_launch(void* const* d_in, const int* in_sizes, int n_in,
                              void* d_out, int out_size)
{
    const float* skip    = (const float*)d_in[0];
    const float* x_up    = (const float*)d_in[1];
    const float* mask    = (const float*)d_in[2];
    const float* kv_w    = (const float*)d_in[3];
    const float* kv_b    = (const float*)d_in[4];
    const float* proj_w  = (const float*)d_in[5];
    const float* proj_b  = (const float*)d_in[6];
    const float* rpb     = (const float*)d_in[7];
    const int*   rel_idx = (const int*)  d_in[8];
    float* out = (float*)d_out;

    float* kvbuf  = nullptr;
    float* ctxbuf = nullptr;
    cudaGetSymbolAddress((void**)&kvbuf,  g_kv);
    cudaGetSymbolAddress((void**)&ctxbuf, g_ctx);

    const int M = B_TOT * NTOK;   // 100352, divisible by 64

    // 1) kv = skip @ kv_w + kv_b   [M,192]x[192,384]
    {
        dim3 grid(384 / 64, M / 64);
        gemm_bias_kernel<<<grid, 256>>>(skip, kv_w, kv_b, kvbuf, DIM, 2 * DIM);
    }

    // 2) fused window attention -> ctx
    {
        dim3 grid(HEADS, B_TOT);
        attn_kernel<<<grid, 128>>>(x_up, mask, rpb, rel_idx, kvbuf, ctxbuf);
    }

    // 3) out = ctx @ proj_w + proj_b   [M,192]x[192,192]
    {
        dim3 grid(DIM / 64, M / 64);
        gemm_bias_kernel<<<grid, 256>>>(ctxbuf, proj_w, proj_b, out, DIM, DIM);
    }
}

// round 3
// speedup vs baseline: 1.3813x; 1.3813x over previous
#include <cuda_runtime.h>
#include <cstddef>

#define B_TOT 1024
#define NTOK  98
#define DIM   192
#define HEADS 6
#define HD    32
#define NW    64
#define TABLE 507

__device__ float g_kv [ (size_t)B_TOT * NTOK * 2 * DIM ];
__device__ float g_ctx[ (size_t)B_TOT * NTOK * DIM ];

// ---------------------------------------------------------------------------
// GEMM v2: C[M,N] = A[M,K] @ W[K,N] + bias. BM=128, BN=64, BK=16, 128 thr,
// 8x8 per-thread register tile, register-staged prefetch of next K-slab.
// ---------------------------------------------------------------------------
#define BM 128
#define BN 64
#define BK 16

__global__ __launch_bounds__(128) void gemm_bias_v2(
    const float* __restrict__ A, const float* __restrict__ W,
    const float* __restrict__ bias, float* __restrict__ C,
    int K, int N)
{
    __shared__ __align__(16) float As[BK][BM];   // [k][m]
    __shared__ __align__(16) float Ws[BK][BN];   // [k][n]

    const int tid = threadIdx.x;
    const int tx  = tid & 7;       // n-group (8 cols each)
    const int ty  = tid >> 3;      // m-group (8 rows each)
    const size_t bm = (size_t)blockIdx.y * BM;
    const int    bn = blockIdx.x * BN;

    const float* Arow = A + (bm + tid) * K;
    const int wr = tid >> 3;          // 0..15  (k row)
    const int wc = (tid & 7) * 8;     // 0..56  (n col, 2 float4)

    float acc[8][8] = {};
    float4 pa[4], pw0, pw1;

    // stage tile 0
    #pragma unroll
    for (int c = 0; c < 4; c++) pa[c] = *(const float4*)&Arow[c * 4];
    pw0 = *(const float4*)&W[(size_t)wr * N + bn + wc];
    pw1 = *(const float4*)&W[(size_t)wr * N + bn + wc + 4];

    const int NT = K / BK;
    for (int t = 0; t < NT; t++) {
        #pragma unroll
        for (int c = 0; c < 4; c++) {
            As[c * 4 + 0][tid] = pa[c].x;
            As[c * 4 + 1][tid] = pa[c].y;
            As[c * 4 + 2][tid] = pa[c].z;
            As[c * 4 + 3][tid] = pa[c].w;
        }
        *(float4*)&Ws[wr][wc]     = pw0;
        *(float4*)&Ws[wr][wc + 4] = pw1;
        __syncthreads();

        if (t + 1 < NT) {
            const int ko = (t + 1) * BK;
            #pragma unroll
            for (int c = 0; c < 4; c++)
                pa[c] = *(const float4*)&Arow[ko + c * 4];
            pw0 = *(const float4*)&W[(size_t)(ko + wr) * N + bn + wc];
            pw1 = *(const float4*)&W[(size_t)(ko + wr) * N + bn + wc + 4];
        }

        #pragma unroll
        for (int k = 0; k < BK; k++) {
            float4 a0 = *(float4*)&As[k][ty * 8];
            float4 a1 = *(float4*)&As[k][ty * 8 + 4];
            float4 b0 = *(float4*)&Ws[k][tx * 8];
            float4 b1 = *(float4*)&Ws[k][tx * 8 + 4];
            float ar[8] = {a0.x, a0.y, a0.z, a0.w, a1.x, a1.y, a1.z, a1.w};
            float br[8] = {b0.x, b0.y, b0.z, b0.w, b1.x, b1.y, b1.z, b1.w};
            #pragma unroll
            for (int i = 0; i < 8; i++)
                #pragma unroll
                for (int j = 0; j < 8; j++)
                    acc[i][j] += ar[i] * br[j];
        }
        __syncthreads();
    }

    float bb[8];
    #pragma unroll
    for (int j = 0; j < 8; j++) bb[j] = bias[bn + tx * 8 + j];
    #pragma unroll
    for (int i = 0; i < 8; i++) {
        float4 o0, o1;
        o0.x = acc[i][0] + bb[0]; o0.y = acc[i][1] + bb[1];
        o0.z = acc[i][2] + bb[2]; o0.w = acc[i][3] + bb[3];
        o1.x = acc[i][4] + bb[4]; o1.y = acc[i][5] + bb[5];
        o1.z = acc[i][6] + bb[6]; o1.w = acc[i][7] + bb[7];
        float* crow = &C[(bm + ty * 8 + i) * N + bn + tx * 8];
        *(float4*)crow       = o0;
        *(float4*)(crow + 4) = o1;
    }
}

// ---------------------------------------------------------------------------
// Attention v2.1: block per (h, b), 128 thr (4 warps). 4-query register
// blocking, float4 smem (all arrays 16B-aligned), fused bias+mask+exp,
// no max-pass (scores bounded), V transposed for conflict-free AV.
// ---------------------------------------------------------------------------
__global__ __launch_bounds__(128) void attn_v2(
    const float* __restrict__ x_up,
    const float* __restrict__ mask,
    const float* __restrict__ rpb,
    const int*   __restrict__ rel_idx,
    const float* __restrict__ kv,
    float*       __restrict__ ctx)
{
    const int h = blockIdx.x;
    const int b = blockIdx.y;

    __shared__ __align__(16) float Ks[NTOK][36];   // K (stride 9 float4)
    __shared__ __align__(16) float Vt[HD][100];    // V^T, cols 98,99 zeroed
    __shared__ __align__(16) float srow[16][100];  // exp(scores)
    __shared__ __align__(16) float qsm[16][HD];    // scaled q rows
    __shared__ __align__(16) float rpb_s[508];     // padded to 16B multiple

    const int tid  = threadIdx.x;
    const int lane = tid & 31;
    const int w    = tid >> 5;

    const float* kvb = kv + (size_t)b * NTOK * 384;

    for (int i = tid; i < NTOK * 8; i += 128) {
        int j = i >> 3, d4 = i & 7;
        *(float4*)&Ks[j][d4 * 4] =
            *(const float4*)&kvb[(size_t)j * 384 + h * HD + d4 * 4];
    }
    for (int i = tid; i < NTOK * 8; i += 128) {
        int j = i >> 3, d4 = i & 7;
        float4 v = *(const float4*)&kvb[(size_t)j * 384 + DIM + h * HD + d4 * 4];
        Vt[d4 * 4 + 0][j] = v.x;
        Vt[d4 * 4 + 1][j] = v.y;
        Vt[d4 * 4 + 2][j] = v.z;
        Vt[d4 * 4 + 3][j] = v.w;
    }
    if (tid < 64) Vt[tid >> 1][98 + (tid & 1)] = 0.f;
    for (int i = tid; i < TABLE; i += 128)
        rpb_s[i] = rpb[(size_t)i * HEADS + h];
    __syncthreads();

    const float scale = 0.1767766952966369f;  // 32^-0.5
    const float* maskw = mask + (size_t)(b & (NW - 1)) * NTOK * NTOK;

    for (int q0 = w * 4; q0 < NTOK; q0 += 16) {
        #pragma unroll
        for (int qi = 0; qi < 4; qi++) {
            int q = q0 + qi;
            float val = 0.f;
            if (q < NTOK)
                val = x_up[((size_t)b * NTOK + q) * DIM + h * HD + lane] * scale;
            qsm[w * 4 + qi][lane] = val;
        }
        __syncwarp();

        // QK^T: acc[qi][t] = q_{q0+qi} . k_{t*32+lane}
        float acc[4][4] = {};
        #pragma unroll
        for (int d4 = 0; d4 < 8; d4++) {
            float4 qf[4];
            #pragma unroll
            for (int qi = 0; qi < 4; qi++)
                qf[qi] = *(float4*)&qsm[w * 4 + qi][d4 * 4];
            #pragma unroll
            for (int t = 0; t < 4; t++) {
                if (t < 3 || lane < 2) {
                    int j = t * 32 + lane;
                    float4 kf = *(float4*)&Ks[j][d4 * 4];
                    #pragma unroll
                    for (int qi = 0; qi < 4; qi++)
                        acc[qi][t] += qf[qi].x * kf.x + qf[qi].y * kf.y +
                                      qf[qi].z * kf.z + qf[qi].w * kf.w;
                }
            }
        }

        // bias + mask + exp + row-sum (no max-pass: scores bounded)
        float inv[4];
        #pragma unroll
        for (int qi = 0; qi < 4; qi++) {
            int q = q0 + qi;
            float ssum = 0.f;
            if (q < NTOK) {
                const int*   relq = rel_idx + q * NTOK;
                const float* mq   = maskw + (size_t)q * NTOK;
                #pragma unroll
                for (int t = 0; t < 4; t++) {
                    int j = t * 32 + lane;
                    if (j < NTOK) {
                        float e = __expf(acc[qi][t] + rpb_s[relq[j]] + mq[j]);
                        srow[w * 4 + qi][j] = e;
                        ssum += e;
                    } else if (j < 100) {
                        srow[w * 4 + qi][j] = 0.f;
                    }
                }
            }
            #pragma unroll
            for (int o = 16; o > 0; o >>= 1)
                ssum += __shfl_xor_sync(0xffffffffu, ssum, o);
            inv[qi] = 1.0f / ssum;
        }
        __syncwarp();

        // AV: out[q][lane] = sum_j p[q][j] * V[j][lane]
        float oacc[4] = {};
        #pragma unroll
        for (int j4 = 0; j4 < 25; j4++) {
            float4 vf = *(float4*)&Vt[lane][j4 * 4];
            #pragma unroll
            for (int qi = 0; qi < 4; qi++) {
                float4 pf = *(float4*)&srow[w * 4 + qi][j4 * 4];
                oacc[qi] += pf.x * vf.x + pf.y * vf.y + pf.z * vf.z + pf.w * vf.w;
            }
        }
        #pragma unroll
        for (int qi = 0; qi < 4; qi++) {
            int q = q0 + qi;
            if (q < NTOK)
                ctx[((size_t)b * NTOK + q) * DIM + h * HD + lane] = oacc[qi] * inv[qi];
        }
        __syncwarp();
    }
}

// ---------------------------------------------------------------------------
extern "C" void kernel_launch(void* const* d_in, const int* in_sizes, int n_in,
                              void* d_out, int out_size)
{
    const float* skip    = (const float*)d_in[0];
    const float* x_up    = (const float*)d_in[1];
    const float* mask    = (const float*)d_in[2];
    const float* kv_w    = (const float*)d_in[3];
    const float* kv_b    = (const float*)d_in[4];
    const float* proj_w  = (const float*)d_in[5];
    const float* proj_b  = (const float*)d_in[6];
    const float* rpb     = (const float*)d_in[7];
    const int*   rel_idx = (const int*)  d_in[8];
    float* out = (float*)d_out;

    float* kvbuf  = nullptr;
    float* ctxbuf = nullptr;
    cudaGetSymbolAddress((void**)&kvbuf,  g_kv);
    cudaGetSymbolAddress((void**)&ctxbuf, g_ctx);

    const int M = B_TOT * NTOK;   // 100352 = 128 * 784

    {   // kv = skip @ kv_w + kv_b   [M,192]x[192,384]
        dim3 grid((2 * DIM) / BN, M / BM);
        gemm_bias_v2<<<grid, 128>>>(skip, kv_w, kv_b, kvbuf, DIM, 2 * DIM);
    }
    {   // fused window attention
        dim3 grid(HEADS, B_TOT);
        attn_v2<<<grid, 128>>>(x_up, mask, rpb, rel_idx, kvbuf, ctxbuf);
    }
    {   // out = ctx @ proj_w + proj_b   [M,192]x[192,192]
        dim3 grid(DIM / BN, M / BM);
        gemm_bias_v2<<<grid, 128>>>(ctxbuf, proj_w, proj_b, out, DIM, DIM);
    }
}

// round 5
// speedup vs baseline: 1.7841x; 1.2916x over previous
#include <cuda_runtime.h>
#include <cuda_bf16.h>
#include <cstdint>
#include <cstddef>

#define B_TOT 1024
#define NTOK  98
#define DIM   192
#define HEADS 6
#define HD    32
#define NW    64
#define TABLE 507

__device__ float g_kv [ (size_t)B_TOT * NTOK * 2 * DIM ];
__device__ float g_ctx[ (size_t)B_TOT * NTOK * DIM ];
// split weights, TRANSPOSED: [k'=576][n], n contiguous. k' = [hi|lo|hi] of k=0..191
__device__ __nv_bfloat16 g_w3kv[(size_t)576 * 384];
__device__ __nv_bfloat16 g_w3pj[(size_t)576 * 192];

// ======================= helpers ===========================================
__device__ __forceinline__ uint32_t smem_u32(const void* p) {
    uint32_t a;
    asm("{ .reg .u64 t; cvta.to.shared.u64 t, %1; cvt.u32.u64 %0, t; }"
        : "=r"(a) : "l"(p));
    return a;
}
__device__ __forceinline__ void ldsm4(uint32_t addr, uint32_t* r) {
    asm volatile("ldmatrix.sync.aligned.m8n8.x4.shared.b16 {%0,%1,%2,%3}, [%4];"
        : "=r"(r[0]), "=r"(r[1]), "=r"(r[2]), "=r"(r[3]) : "r"(addr));
}
__device__ __forceinline__ void ldsm4t(uint32_t addr, uint32_t* r) {
    asm volatile("ldmatrix.sync.aligned.m8n8.x4.trans.shared.b16 {%0,%1,%2,%3}, [%4];"
        : "=r"(r[0]), "=r"(r[1]), "=r"(r[2]), "=r"(r[3]) : "r"(addr));
}
__device__ __forceinline__ void mma16816(float* c, const uint32_t* a,
                                         uint32_t b0, uint32_t b1) {
    asm volatile("mma.sync.aligned.m16n8k16.row.col.f32.bf16.bf16.f32 "
        "{%0,%1,%2,%3}, {%4,%5,%6,%7}, {%8,%9}, {%0,%1,%2,%3};"
        : "+f"(c[0]), "+f"(c[1]), "+f"(c[2]), "+f"(c[3])
        : "r"(a[0]), "r"(a[1]), "r"(a[2]), "r"(a[3]), "r"(b0), "r"(b1));
}

// ======================= weight split + transpose ==========================
__global__ void build_w3t(const float* __restrict__ W, __nv_bfloat16* __restrict__ w3t, int N)
{
    int idx = blockIdx.x * 256 + threadIdx.x;
    if (idx >= 192 * N) return;
    int k = idx / N, n = idx % N;
    float a = W[idx];
    __nv_bfloat16 hi = __float2bfloat16_rn(a);
    __nv_bfloat16 lo = __float2bfloat16_rn(a - __bfloat162float(hi));
    w3t[(size_t)k * N + n]         = hi;   // k'  0..191 : W_hi
    w3t[(size_t)(192 + k) * N + n] = lo;   // k' 192..383: W_lo   (paired with A_hi)
    w3t[(size_t)(384 + k) * N + n] = hi;   // k' 384..575: W_hi   (paired with A_lo)
}

// ======================= mma.sync GEMM =====================================
// C[M, N] = split3(A[M,192]) @ W3T + bias.  CTA: 128m x 64n, 256 thr (8 warps,
// warp tile 32x32), K'=576 in 9 chunks of 64. A split hi/lo while staging.
__global__ __launch_bounds__(256) void gemm_mma(
    const float* __restrict__ A,
    const __nv_bfloat16* __restrict__ W3T,   // [576][N]
    const float* __restrict__ bias,
    float* __restrict__ C, int N)
{
    __shared__ __align__(16) __nv_bfloat16 As[128][72];
    __shared__ __align__(16) __nv_bfloat16 Bs[64][72];

    const int tid  = threadIdx.x;
    const int lane = tid & 31;
    const int w    = tid >> 5;
    const size_t bm = (size_t)blockIdx.y * 128;
    const int    bn = blockIdx.x * 64;

    const int m0 = (w & 3) * 32;     // warp m offset
    const int n0 = (w >> 2) * 32;    // warp n offset

    // ldmatrix source addresses (per lane)
    const uint32_t a_base = smem_u32(As) +
        (( (lane & 7) + ((lane & 8) ? 8 : 0) + m0) * 72 + ((lane >> 4) * 8)) * 2;
    const uint32_t b_base = smem_u32(Bs) +
        (( (lane & 7) + ((lane & 8) ? 8 : 0)) * 72 + n0 + (lane >> 4) * 8) * 2;

    float acc[2][4][4] = {};

    for (int c = 0; c < 9; c++) {
        __syncthreads();
        // --- stage A chunk (128 x 64), fp32 -> bf16 hi/lo split ---
        const int  k0     = (c % 3) * 64;
        const bool use_lo = (c >= 6);
        #pragma unroll
        for (int o = tid; o < 128 * 8; o += 256) {
            int row = o >> 3, cg = (o & 7) * 8;
            const float* ap = &A[(bm + row) * 192 + k0 + cg];
            float4 f0 = *(const float4*)ap;
            float4 f1 = *(const float4*)(ap + 4);
            float v[8] = {f0.x, f0.y, f0.z, f0.w, f1.x, f1.y, f1.z, f1.w};
            union { __nv_bfloat16 h[8]; uint4 u; } pk;
            #pragma unroll
            for (int i = 0; i < 8; i++) {
                __nv_bfloat16 hi = __float2bfloat16_rn(v[i]);
                pk.h[i] = use_lo ? __float2bfloat16_rn(v[i] - __bfloat162float(hi)) : hi;
            }
            *(uint4*)&As[row][cg] = pk.u;
        }
        // --- stage B chunk (64 k-rows x 64 n) from transposed split table ---
        #pragma unroll
        for (int o = tid; o < 64 * 8; o += 256) {
            int kk = o >> 3, cg = (o & 7) * 8;
            *(uint4*)&Bs[kk][cg] =
                *(const uint4*)&W3T[(size_t)(c * 64 + kk) * N + bn + cg];
        }
        __syncthreads();

        // --- compute: 4 k16 steps ---
        #pragma unroll
        for (int ks = 0; ks < 4; ks++) {
            const int k16 = ks * 16;
            uint32_t a[2][4];
            ldsm4(a_base + (uint32_t)(k16 * 2),            a[0]);
            ldsm4(a_base + (uint32_t)((16 * 72 + k16) * 2), a[1]);
            uint32_t b[2][4];
            ldsm4t(b_base + (uint32_t)(k16 * 72 * 2),        b[0]);
            ldsm4t(b_base + (uint32_t)(k16 * 72 * 2 + 32),   b[1]);  // +16 cols
            #pragma unroll
            for (int mi = 0; mi < 2; mi++) {
                mma16816(acc[mi][0], a[mi], b[0][0], b[0][1]);
                mma16816(acc[mi][1], a[mi], b[0][2], b[0][3]);
                mma16816(acc[mi][2], a[mi], b[1][0], b[1][1]);
                mma16816(acc[mi][3], a[mi], b[1][2], b[1][3]);
            }
        }
    }

    // --- epilogue: c frag rows l>>2 (+8), cols 2*(l&3)(+1) ---
    #pragma unroll
    for (int mi = 0; mi < 2; mi++) {
        const size_t row0 = bm + m0 + mi * 16 + (lane >> 2);
        #pragma unroll
        for (int ni = 0; ni < 4; ni++) {
            const int col = bn + n0 + ni * 8 + 2 * (lane & 3);
            float2 bv = *(const float2*)&bias[col];
            float2 o0 = {acc[mi][ni][0] + bv.x, acc[mi][ni][1] + bv.y};
            float2 o1 = {acc[mi][ni][2] + bv.x, acc[mi][ni][3] + bv.y};
            *(float2*)&C[row0 * N + col]       = o0;
            *(float2*)&C[(row0 + 8) * N + col] = o1;
        }
    }
}

// ======================= attention (unchanged, known-good) =================
__global__ __launch_bounds__(128) void attn_v2(
    const float* __restrict__ x_up,
    const float* __restrict__ mask,
    const float* __restrict__ rpb,
    const int*   __restrict__ rel_idx,
    const float* __restrict__ kv,
    float*       __restrict__ ctx)
{
    const int h = blockIdx.x;
    const int b = blockIdx.y;

    __shared__ __align__(16) float Ks[NTOK][36];
    __shared__ __align__(16) float Vt[HD][100];
    __shared__ __align__(16) float srow[16][100];
    __shared__ __align__(16) float qsm[16][HD];
    __shared__ __align__(16) float rpb_s[508];

    const int tid  = threadIdx.x;
    const int lane = tid & 31;
    const int w    = tid >> 5;

    const float* kvb = kv + (size_t)b * NTOK * 384;

    for (int i = tid; i < NTOK * 8; i += 128) {
        int j = i >> 3, d4 = i & 7;
        *(float4*)&Ks[j][d4 * 4] =
            *(const float4*)&kvb[(size_t)j * 384 + h * HD + d4 * 4];
    }
    for (int i = tid; i < NTOK * 8; i += 128) {
        int j = i >> 3, d4 = i & 7;
        float4 v = *(const float4*)&kvb[(size_t)j * 384 + DIM + h * HD + d4 * 4];
        Vt[d4 * 4 + 0][j] = v.x;
        Vt[d4 * 4 + 1][j] = v.y;
        Vt[d4 * 4 + 2][j] = v.z;
        Vt[d4 * 4 + 3][j] = v.w;
    }
    if (tid < 64) Vt[tid >> 1][98 + (tid & 1)] = 0.f;
    for (int i = tid; i < TABLE; i += 128)
        rpb_s[i] = rpb[(size_t)i * HEADS + h];
    __syncthreads();

    const float scale = 0.1767766952966369f;
    const float* maskw = mask + (size_t)(b & (NW - 1)) * NTOK * NTOK;

    for (int q0 = w * 4; q0 < NTOK; q0 += 16) {
        #pragma unroll
        for (int qi = 0; qi < 4; qi++) {
            int q = q0 + qi;
            float val = 0.f;
            if (q < NTOK)
                val = x_up[((size_t)b * NTOK + q) * DIM + h * HD + lane] * scale;
            qsm[w * 4 + qi][lane] = val;
        }
        __syncwarp();

        float acc[4][4] = {};
        #pragma unroll
        for (int d4 = 0; d4 < 8; d4++) {
            float4 qf[4];
            #pragma unroll
            for (int qi = 0; qi < 4; qi++)
                qf[qi] = *(float4*)&qsm[w * 4 + qi][d4 * 4];
            #pragma unroll
            for (int t = 0; t < 4; t++) {
                if (t < 3 || lane < 2) {
                    int j = t * 32 + lane;
                    float4 kf = *(float4*)&Ks[j][d4 * 4];
                    #pragma unroll
                    for (int qi = 0; qi < 4; qi++)
                        acc[qi][t] += qf[qi].x * kf.x + qf[qi].y * kf.y +
                                      qf[qi].z * kf.z + qf[qi].w * kf.w;
                }
            }
        }

        float inv[4];
        #pragma unroll
        for (int qi = 0; qi < 4; qi++) {
            int q = q0 + qi;
            float ssum = 0.f;
            if (q < NTOK) {
                const int*   relq = rel_idx + q * NTOK;
                const float* mq   = maskw + (size_t)q * NTOK;
                #pragma unroll
                for (int t = 0; t < 4; t++) {
                    int j = t * 32 + lane;
                    if (j < NTOK) {
                        float e = __expf(acc[qi][t] + rpb_s[relq[j]] + mq[j]);
                        srow[w * 4 + qi][j] = e;
                        ssum += e;
                    } else if (j < 100) {
                        srow[w * 4 + qi][j] = 0.f;
                    }
                }
            }
            #pragma unroll
            for (int o = 16; o > 0; o >>= 1)
                ssum += __shfl_xor_sync(0xffffffffu, ssum, o);
            inv[qi] = 1.0f / ssum;
        }
        __syncwarp();

        float oacc[4] = {};
        #pragma unroll
        for (int j4 = 0; j4 < 25; j4++) {
            float4 vf = *(float4*)&Vt[lane][j4 * 4];
            #pragma unroll
            for (int qi = 0; qi < 4; qi++) {
                float4 pf = *(float4*)&srow[w * 4 + qi][j4 * 4];
                oacc[qi] += pf.x * vf.x + pf.y * vf.y + pf.z * vf.z + pf.w * vf.w;
            }
        }
        #pragma unroll
        for (int qi = 0; qi < 4; qi++) {
            int q = q0 + qi;
            if (q < NTOK)
                ctx[((size_t)b * NTOK + q) * DIM + h * HD + lane] = oacc[qi] * inv[qi];
        }
        __syncwarp();
    }
}

// ---------------------------------------------------------------------------
extern "C" void kernel_launch(void* const* d_in, const int* in_sizes, int n_in,
                              void* d_out, int out_size)
{
    const float* skip    = (const float*)d_in[0];
    const float* x_up    = (const float*)d_in[1];
    const float* mask    = (const float*)d_in[2];
    const float* kv_w    = (const float*)d_in[3];
    const float* kv_b    = (const float*)d_in[4];
    const float* proj_w  = (const float*)d_in[5];
    const float* proj_b  = (const float*)d_in[6];
    const float* rpb     = (const float*)d_in[7];
    const int*   rel_idx = (const int*)  d_in[8];
    float* out = (float*)d_out;

    float *kvbuf = nullptr, *ctxbuf = nullptr;
    __nv_bfloat16 *w3kv = nullptr, *w3pj = nullptr;
    cudaGetSymbolAddress((void**)&kvbuf,  g_kv);
    cudaGetSymbolAddress((void**)&ctxbuf, g_ctx);
    cudaGetSymbolAddress((void**)&w3kv,   g_w3kv);
    cudaGetSymbolAddress((void**)&w3pj,   g_w3pj);

    const int M = B_TOT * NTOK;   // 100352 = 784 * 128

    // split + transpose weights (tiny, one-time cost per call)
    build_w3t<<<(192 * 384 + 255) / 256, 256>>>(kv_w,   w3kv, 384);
    build_w3t<<<(192 * 192 + 255) / 256, 256>>>(proj_w, w3pj, 192);

    // kv = split3(skip) @ w3kv + kv_b
    {
        dim3 grid(384 / 64, M / 128);
        gemm_mma<<<grid, 256>>>(skip, w3kv, kv_b, kvbuf, 384);
    }
    // fused window attention
    {
        dim3 grid(HEADS, B_TOT);
        attn_v2<<<grid, 128>>>(x_up, mask, rpb, rel_idx, kvbuf, ctxbuf);
    }
    // out = split3(ctx) @ w3pj + proj_b
    {
        dim3 grid(192 / 64, M / 128);
        gemm_mma<<<grid, 256>>>(ctxbuf, w3pj, proj_b, out, 192);
    }
}

// round 6
// speedup vs baseline: 1.8412x; 1.0320x over previous
#include <cuda_runtime.h>
#include <cuda_bf16.h>
#include <cstdint>
#include <cstddef>

#define B_TOT 1024
#define NTOK  98
#define DIM   192
#define HEADS 6
#define HD    32
#define NW    64
#define TABLE 507

__device__ float g_kv [ (size_t)B_TOT * NTOK * 2 * DIM ];
__device__ float g_ctx[ (size_t)B_TOT * NTOK * DIM ];
__device__ __nv_bfloat16 g_w3kv[(size_t)576 * 384];
__device__ __nv_bfloat16 g_w3pj[(size_t)576 * 192];
__device__ float g_cbias[(size_t)NW * HEADS * NTOK * NTOK];   // 14.75 MB

// ======================= helpers ===========================================
__device__ __forceinline__ uint32_t smem_u32(const void* p) {
    uint32_t a;
    asm("{ .reg .u64 t; cvta.to.shared.u64 t, %1; cvt.u32.u64 %0, t; }"
        : "=r"(a) : "l"(p));
    return a;
}
__device__ __forceinline__ void ldsm4(uint32_t addr, uint32_t* r) {
    asm volatile("ldmatrix.sync.aligned.m8n8.x4.shared.b16 {%0,%1,%2,%3}, [%4];"
        : "=r"(r[0]), "=r"(r[1]), "=r"(r[2]), "=r"(r[3]) : "r"(addr));
}
__device__ __forceinline__ void ldsm4t(uint32_t addr, uint32_t* r) {
    asm volatile("ldmatrix.sync.aligned.m8n8.x4.trans.shared.b16 {%0,%1,%2,%3}, [%4];"
        : "=r"(r[0]), "=r"(r[1]), "=r"(r[2]), "=r"(r[3]) : "r"(addr));
}
__device__ __forceinline__ void mma16816(float* c, const uint32_t* a,
                                         uint32_t b0, uint32_t b1) {
    asm volatile("mma.sync.aligned.m16n8k16.row.col.f32.bf16.bf16.f32 "
        "{%0,%1,%2,%3}, {%4,%5,%6,%7}, {%8,%9}, {%0,%1,%2,%3};"
        : "+f"(c[0]), "+f"(c[1]), "+f"(c[2]), "+f"(c[3])
        : "r"(a[0]), "r"(a[1]), "r"(a[2]), "r"(a[3]), "r"(b0), "r"(b1));
}
// pack {lo, hi} floats -> bf16x2 register (lo in low half)
__device__ __forceinline__ uint32_t packbf(float lo, float hi) {
    uint32_t r;
    asm("cvt.rn.bf16x2.f32 %0, %1, %2;" : "=r"(r) : "f"(hi), "f"(lo));
    return r;
}

// ======================= weight split + transpose ==========================
__global__ void build_w3t(const float* __restrict__ W, __nv_bfloat16* __restrict__ w3t, int N)
{
    int idx = blockIdx.x * 256 + threadIdx.x;
    if (idx >= 192 * N) return;
    int k = idx / N, n = idx % N;
    float a = W[idx];
    __nv_bfloat16 hi = __float2bfloat16_rn(a);
    __nv_bfloat16 lo = __float2bfloat16_rn(a - __bfloat162float(hi));
    w3t[(size_t)k * N + n]         = hi;
    w3t[(size_t)(192 + k) * N + n] = lo;
    w3t[(size_t)(384 + k) * N + n] = hi;
}

// ======================= combined bias precompute ==========================
// cb[w][h][q][k] = mask[w][q][k] + rpb[rel_idx[q][k]][h]
__global__ void build_cbias(const float* __restrict__ mask,
                            const float* __restrict__ rpb,
                            const int*   __restrict__ rel_idx,
                            float* __restrict__ cb)
{
    int idx = blockIdx.x * 256 + threadIdx.x;
    if (idx >= NW * HEADS * NTOK * NTOK) return;
    int k = idx % NTOK;
    int t = idx / NTOK;
    int q = t % NTOK;  t /= NTOK;
    int h = t % HEADS; int w = t / HEADS;
    cb[idx] = mask[((size_t)w * NTOK + q) * NTOK + k] +
              rpb[(size_t)rel_idx[q * NTOK + k] * HEADS + h];
}

// ======================= mma.sync GEMM (templated BN) ======================
template<int BN>
__global__ __launch_bounds__(256) void gemm_mma(
    const float* __restrict__ A,
    const __nv_bfloat16* __restrict__ W3T,   // [576][N]
    const float* __restrict__ bias,
    float* __restrict__ C, int N)
{
    constexpr int SB  = BN + 8;
    constexpr int NFR = BN / 16;             // n8 frags per warp (warp n = BN/2)
    __shared__ __align__(16) __nv_bfloat16 As[128][72];
    __shared__ __align__(16) __nv_bfloat16 Bs[64][SB];

    const int tid  = threadIdx.x;
    const int lane = tid & 31;
    const int w    = tid >> 5;
    const int wm   = w & 3, wn = w >> 2;
    const size_t bm = (size_t)blockIdx.y * 128;
    const int    bn = blockIdx.x * BN;
    const int m0 = wm * 32, n0 = wn * (BN / 2);

    const uint32_t qrow = (lane & 7) + ((lane & 8) ? 8 : 0);
    const uint32_t a_base = smem_u32(As) + ((qrow + m0) * 72 + (lane >> 4) * 8) * 2;
    const uint32_t b_base = smem_u32(Bs) + (qrow * SB + n0 + (lane >> 4) * 8) * 2;

    float acc[2][NFR][4] = {};

    const int sched[9] = {0, 3, 1, 4, 2, 5, 6, 7, 8};
    #pragma unroll 1
    for (int s = 0; s < 9; s++) {
        const int c = sched[s];
        const bool newA = !(s == 1 || s == 3 || s == 5);
        __syncthreads();
        if (newA) {
            const int  k0     = (c % 3) * 64;
            const bool use_lo = (c >= 6);
            #pragma unroll
            for (int o = tid; o < 1024; o += 256) {
                int row = o >> 3, cg = (o & 7) * 8;
                const float* ap = &A[(bm + row) * 192 + k0 + cg];
                float4 f0 = *(const float4*)ap;
                float4 f1 = *(const float4*)(ap + 4);
                float v[8] = {f0.x, f0.y, f0.z, f0.w, f1.x, f1.y, f1.z, f1.w};
                union { __nv_bfloat16 hh[8]; uint4 u; } pk;
                #pragma unroll
                for (int i = 0; i < 8; i++) {
                    __nv_bfloat16 hi = __float2bfloat16_rn(v[i]);
                    pk.hh[i] = use_lo ? __float2bfloat16_rn(v[i] - __bfloat162float(hi)) : hi;
                }
                *(uint4*)&As[row][cg] = pk.u;
            }
        }
        #pragma unroll
        for (int o = tid; o < 64 * (BN / 8); o += 256) {
            int kk = o / (BN / 8), cg = (o % (BN / 8)) * 8;
            *(uint4*)&Bs[kk][cg] =
                *(const uint4*)&W3T[(size_t)(c * 64 + kk) * N + bn + cg];
        }
        __syncthreads();

        #pragma unroll
        for (int ks = 0; ks < 4; ks++) {
            uint32_t a[2][4];
            ldsm4(a_base + (uint32_t)(ks * 16 * 2),            a[0]);
            ldsm4(a_base + (uint32_t)((16 * 72 + ks * 16) * 2), a[1]);
            #pragma unroll
            for (int nb = 0; nb < NFR / 2; nb++) {
                uint32_t bq[4];
                ldsm4t(b_base + (uint32_t)((ks * 16 * SB + nb * 16) * 2), bq);
                #pragma unroll
                for (int mi = 0; mi < 2; mi++) {
                    mma16816(acc[mi][2 * nb],     a[mi], bq[0], bq[1]);
                    mma16816(acc[mi][2 * nb + 1], a[mi], bq[2], bq[3]);
                }
            }
        }
    }

    #pragma unroll
    for (int mi = 0; mi < 2; mi++) {
        const size_t row0 = bm + m0 + mi * 16 + (lane >> 2);
        #pragma unroll
        for (int ni = 0; ni < NFR; ni++) {
            const int col = bn + n0 + ni * 8 + 2 * (lane & 3);
            float2 bv = *(const float2*)&bias[col];
            *(float2*)&C[row0 * N + col] =
                make_float2(acc[mi][ni][0] + bv.x, acc[mi][ni][1] + bv.y);
            *(float2*)&C[(row0 + 8) * N + col] =
                make_float2(acc[mi][ni][2] + bv.x, acc[mi][ni][3] + bv.y);
        }
    }
}

// ======================= mma.sync attention ================================
// CTA per (h, b). 4 warps, warp m-tile 32 (M padded 128), keys padded 112.
// S = QK^T via 3-term bf16 split; exp fused with precomputed cbias; PV via
// FA2 register trick (C frags -> A frags), P split hi/lo, 3-term bf16.
__global__ __launch_bounds__(128) void attn_mma(
    const float* __restrict__ x_up,
    const float* __restrict__ kv,
    const float* __restrict__ cbias,
    float*       __restrict__ ctx)
{
    const int h = blockIdx.x;
    const int b = blockIdx.y;

    extern __shared__ __align__(16) char smem[];
    __nv_bfloat16* QH = (__nv_bfloat16*)smem;          // [128][40]
    __nv_bfloat16* QL = QH + 128 * 40;
    __nv_bfloat16* KH = QL + 128 * 40;                 // [32][120] (K^T)
    __nv_bfloat16* KL = KH + 32 * 120;
    __nv_bfloat16* VH = KL + 32 * 120;                 // [112][40]
    __nv_bfloat16* VL = VH + 112 * 40;

    const int tid  = threadIdx.x;
    const int lane = tid & 31;
    const int w    = tid >> 5;
    const float scale = 0.1767766952966369f;
    const __nv_bfloat16 bz = __float2bfloat16_rn(0.f);

    const float* xb  = x_up + ((size_t)b * NTOK) * DIM + h * HD;
    const float* kvb = kv + (size_t)b * NTOK * 384;

    // ---- stage Q (scaled, hi/lo), rows 98..127 zero ----
    for (int o = tid; o < 1024; o += 128) {
        int row = o >> 3, c4 = (o & 7) * 4;
        uint2 ph = make_uint2(0, 0), pl = make_uint2(0, 0);
        if (row < NTOK) {
            float4 f = *(const float4*)(xb + (size_t)row * DIM + c4);
            float v[4] = {f.x * scale, f.y * scale, f.z * scale, f.w * scale};
            union { __nv_bfloat16 h2[4]; uint2 u; } a, bb;
            #pragma unroll
            for (int i = 0; i < 4; i++) {
                __nv_bfloat16 hi = __float2bfloat16_rn(v[i]);
                a.h2[i]  = hi;
                bb.h2[i] = __float2bfloat16_rn(v[i] - __bfloat162float(hi));
            }
            ph = a.u; pl = bb.u;
        }
        *(uint2*)(QH + row * 40 + c4) = ph;
        *(uint2*)(QL + row * 40 + c4) = pl;
    }
    // ---- stage K transposed (hi/lo) ----
    for (int o = tid; o < 784; o += 128) {
        int j = o >> 3, c4 = (o & 7) * 4;
        float4 f = *(const float4*)(kvb + (size_t)j * 384 + h * HD + c4);
        float v[4] = {f.x, f.y, f.z, f.w};
        #pragma unroll
        for (int i = 0; i < 4; i++) {
            __nv_bfloat16 hi = __float2bfloat16_rn(v[i]);
            KH[(c4 + i) * 120 + j] = hi;
            KL[(c4 + i) * 120 + j] = __float2bfloat16_rn(v[i] - __bfloat162float(hi));
        }
    }
    for (int o = tid; o < 448; o += 128) {       // zero K cols 98..111
        int d = o / 14, j = 98 + (o % 14);
        KH[d * 120 + j] = bz; KL[d * 120 + j] = bz;
    }
    // ---- stage V (hi/lo), rows 98..111 zero ----
    for (int o = tid; o < 784; o += 128) {
        int j = o >> 3, c4 = (o & 7) * 4;
        float4 f = *(const float4*)(kvb + (size_t)j * 384 + DIM + h * HD + c4);
        float v[4] = {f.x, f.y, f.z, f.w};
        union { __nv_bfloat16 h2[4]; uint2 u; } a, bb;
        #pragma unroll
        for (int i = 0; i < 4; i++) {
            __nv_bfloat16 hi = __float2bfloat16_rn(v[i]);
            a.h2[i]  = hi;
            bb.h2[i] = __float2bfloat16_rn(v[i] - __bfloat162float(hi));
        }
        *(uint2*)(VH + j * 40 + c4) = a.u;
        *(uint2*)(VL + j * 40 + c4) = bb.u;
    }
    for (int o = tid; o < 448; o += 128) {       // zero V rows 98..111
        int j = 98 + o / 32, c = o & 31;
        VH[j * 40 + c] = bz; VL[j * 40 + c] = bz;
    }
    __syncthreads();

    // ---- S = QK^T (3-term split) ----
    const int m0 = w * 32;
    const uint32_t qrow = (lane & 7) + ((lane & 8) ? 8 : 0);
    const uint32_t acol = (lane >> 4) * 8;
    const uint32_t aH = smem_u32(QH) + ((m0 + qrow) * 40 + acol) * 2;
    const uint32_t aL = aH + 128 * 40 * 2;
    const uint32_t bKH = smem_u32(KH) + (qrow * 120 + acol) * 2;
    const uint32_t bKL = bKH + 32 * 120 * 2;

    float acc[2][14][4] = {};
    #pragma unroll
    for (int k16 = 0; k16 < 2; k16++) {
        uint32_t ah[2][4], al[2][4];
        ldsm4(aH + (uint32_t)(k16 * 16 * 2),             ah[0]);
        ldsm4(aH + (uint32_t)((16 * 40 + k16 * 16) * 2), ah[1]);
        ldsm4(aL + (uint32_t)(k16 * 16 * 2),             al[0]);
        ldsm4(aL + (uint32_t)((16 * 40 + k16 * 16) * 2), al[1]);
        #pragma unroll
        for (int nb = 0; nb < 7; nb++) {
            uint32_t bh[4], bl[4];
            ldsm4t(bKH + (uint32_t)((k16 * 16 * 120 + nb * 16) * 2), bh);
            ldsm4t(bKL + (uint32_t)((k16 * 16 * 120 + nb * 16) * 2), bl);
            #pragma unroll
            for (int mi = 0; mi < 2; mi++) {
                mma16816(acc[mi][2 * nb],     ah[mi], bh[0], bh[1]);
                mma16816(acc[mi][2 * nb + 1], ah[mi], bh[2], bh[3]);
                mma16816(acc[mi][2 * nb],     al[mi], bh[0], bh[1]);
                mma16816(acc[mi][2 * nb + 1], al[mi], bh[2], bh[3]);
                mma16816(acc[mi][2 * nb],     ah[mi], bl[0], bl[1]);
                mma16816(acc[mi][2 * nb + 1], ah[mi], bl[2], bl[3]);
            }
        }
    }

    // ---- bias + exp + row sums ----
    const int r0 = m0 + (lane >> 2);
    const float* cbq = cbias + (((size_t)(b & (NW - 1)) * HEADS + h) * NTOK) * NTOK;
    float inv[2][2];
    #pragma unroll
    for (int mi = 0; mi < 2; mi++) {
        const int ra = r0 + mi * 16, rb = ra + 8;
        const bool okA = ra < NTOK, okB = rb < NTOK;
        const float* pA = cbq + (size_t)ra * NTOK;
        const float* pB = cbq + (size_t)rb * NTOK;
        float sA = 0.f, sB = 0.f;
        #pragma unroll
        for (int ni = 0; ni < 14; ni++) {
            const int c0 = ni * 8 + 2 * (lane & 3);
            const bool okC = c0 < NTOK;
            float e0 = 0.f, e1 = 0.f, e2 = 0.f, e3 = 0.f;
            if (okA && okC) {
                float2 cb = *(const float2*)(pA + c0);
                e0 = __expf(acc[mi][ni][0] + cb.x);
                e1 = __expf(acc[mi][ni][1] + cb.y);
            }
            if (okB && okC) {
                float2 cb = *(const float2*)(pB + c0);
                e2 = __expf(acc[mi][ni][2] + cb.x);
                e3 = __expf(acc[mi][ni][3] + cb.y);
            }
            sA += e0 + e1; sB += e2 + e3;
            acc[mi][ni][0] = e0; acc[mi][ni][1] = e1;
            acc[mi][ni][2] = e2; acc[mi][ni][3] = e3;
        }
        sA += __shfl_xor_sync(0xffffffffu, sA, 1);
        sA += __shfl_xor_sync(0xffffffffu, sA, 2);
        sB += __shfl_xor_sync(0xffffffffu, sB, 1);
        sB += __shfl_xor_sync(0xffffffffu, sB, 2);
        inv[mi][0] = 1.f / sA; inv[mi][1] = 1.f / sB;
    }

    // ---- O = P V (3-term split, P from registers) ----
    float o[2][4][4] = {};
    const uint32_t bVH = smem_u32(VH) + (qrow * 40 + acol) * 2;
    const uint32_t bVL = bVH + 112 * 40 * 2;
    #pragma unroll
    for (int g = 0; g < 7; g++) {
        uint32_t ph[2][4], pl[2][4];
        #pragma unroll
        for (int mi = 0; mi < 2; mi++) {
            const float* cA = acc[mi][2 * g];
            const float* cB = acc[mi][2 * g + 1];
            #pragma unroll
            for (int t = 0; t < 2; t++) {
                const float* cc = t ? cB : cA;
                uint32_t p0 = packbf(cc[0], cc[1]);
                uint32_t p1 = packbf(cc[2], cc[3]);
                ph[mi][2 * t]     = p0;
                ph[mi][2 * t + 1] = p1;
                pl[mi][2 * t]     = packbf(cc[0] - __uint_as_float(p0 << 16),
                                           cc[1] - __uint_as_float(p0 & 0xFFFF0000u));
                pl[mi][2 * t + 1] = packbf(cc[2] - __uint_as_float(p1 << 16),
                                           cc[3] - __uint_as_float(p1 & 0xFFFF0000u));
            }
        }
        uint32_t vh0[4], vh1[4], vl0[4], vl1[4];
        ldsm4t(bVH + (uint32_t)(g * 16 * 40 * 2),        vh0);
        ldsm4t(bVH + (uint32_t)((g * 16 * 40 + 16) * 2), vh1);
        ldsm4t(bVL + (uint32_t)(g * 16 * 40 * 2),        vl0);
        ldsm4t(bVL + (uint32_t)((g * 16 * 40 + 16) * 2), vl1);
        #pragma unroll
        for (int mi = 0; mi < 2; mi++) {
            mma16816(o[mi][0], ph[mi], vh0[0], vh0[1]);
            mma16816(o[mi][1], ph[mi], vh0[2], vh0[3]);
            mma16816(o[mi][2], ph[mi], vh1[0], vh1[1]);
            mma16816(o[mi][3], ph[mi], vh1[2], vh1[3]);
            mma16816(o[mi][0], pl[mi], vh0[0], vh0[1]);
            mma16816(o[mi][1], pl[mi], vh0[2], vh0[3]);
            mma16816(o[mi][2], pl[mi], vh1[0], vh1[1]);
            mma16816(o[mi][3], pl[mi], vh1[2], vh1[3]);
            mma16816(o[mi][0], ph[mi], vl0[0], vl0[1]);
            mma16816(o[mi][1], ph[mi], vl0[2], vl0[3]);
            mma16816(o[mi][2], ph[mi], vl1[0], vl1[1]);
            mma16816(o[mi][3], ph[mi], vl1[2], vl1[3]);
        }
    }

    // ---- store ----
    #pragma unroll
    for (int mi = 0; mi < 2; mi++) {
        const int ra = r0 + mi * 16, rb = ra + 8;
        #pragma unroll
        for (int vn = 0; vn < 4; vn++) {
            const int col = h * HD + vn * 8 + 2 * (lane & 3);
            if (ra < NTOK)
                *(float2*)(ctx + ((size_t)b * NTOK + ra) * DIM + col) =
                    make_float2(o[mi][vn][0] * inv[mi][0], o[mi][vn][1] * inv[mi][0]);
            if (rb < NTOK)
                *(float2*)(ctx + ((size_t)b * NTOK + rb) * DIM + col) =
                    make_float2(o[mi][vn][2] * inv[mi][1], o[mi][vn][3] * inv[mi][1]);
        }
    }
}

// ---------------------------------------------------------------------------
extern "C" void kernel_launch(void* const* d_in, const int* in_sizes, int n_in,
                              void* d_out, int out_size)
{
    const float* skip    = (const float*)d_in[0];
    const float* x_up    = (const float*)d_in[1];
    const float* mask    = (const float*)d_in[2];
    const float* kv_w    = (const float*)d_in[3];
    const float* kv_b    = (const float*)d_in[4];
    const float* proj_w  = (const float*)d_in[5];
    const float* proj_b  = (const float*)d_in[6];
    const float* rpb     = (const float*)d_in[7];
    const int*   rel_idx = (const int*)  d_in[8];
    float* out = (float*)d_out;

    float *kvbuf = nullptr, *ctxbuf = nullptr, *cbbuf = nullptr;
    __nv_bfloat16 *w3kv = nullptr, *w3pj = nullptr;
    cudaGetSymbolAddress((void**)&kvbuf,  g_kv);
    cudaGetSymbolAddress((void**)&ctxbuf, g_ctx);
    cudaGetSymbolAddress((void**)&w3kv,   g_w3kv);
    cudaGetSymbolAddress((void**)&w3pj,   g_w3pj);
    cudaGetSymbolAddress((void**)&cbbuf,  g_cbias);

    const int M = B_TOT * NTOK;   // 100352 = 784 * 128
    const int ATTN_SMEM = (2 * 128 * 40 + 2 * 32 * 120 + 2 * 112 * 40) * 2;  // 53760
    cudaFuncSetAttribute(attn_mma, cudaFuncAttributeMaxDynamicSharedMemorySize, ATTN_SMEM);

    // precompute tables
    build_w3t<<<(192 * 384 + 255) / 256, 256>>>(kv_w,   w3kv, 384);
    build_w3t<<<(192 * 192 + 255) / 256, 256>>>(proj_w, w3pj, 192);
    build_cbias<<<(NW * HEADS * NTOK * NTOK + 255) / 256, 256>>>(mask, rpb, rel_idx, cbbuf);

    // kv = split3(skip) @ w3kv + kv_b
    {
        dim3 grid(384 / 128, M / 128);
        gemm_mma<128><<<grid, 256>>>(skip, w3kv, kv_b, kvbuf, 384);
    }
    // attention
    {
        dim3 grid(HEADS, B_TOT);
        attn_mma<<<grid, 128, ATTN_SMEM>>>(x_up, kvbuf, cbbuf, ctxbuf);
    }
    // out = split3(ctx) @ w3pj + proj_b
    {
        dim3 grid(1, M / 128);
        gemm_mma<192><<<grid, 256>>>(ctxbuf, w3pj, proj_b, out, 192);
    }
}